// round 5
// baseline (speedup 1.0000x reference)
#include <cuda_runtime.h>
#include <cuda_bf16.h>
#include <math.h>

#define NB 8
#define CC 128
#define LL 4096
#define NL (NB * LL)          // 32768
#define LSPLIT 8
#define EPS_BAND 1e-5f

// ---------------- scratch (device globals; no dynamic allocation) ------------
// NOTE: these symbols are referenced ONLY in device code. Taking their address
// in host code yields the host shadow address, which GB300's ATS silently
// accepts — writes then land in Grace CPU memory, not the device symbol.
__device__ float g_ymu[CC];
__device__ float g_xn[(size_t)NB * CC * LL];           // 16 MB
__device__ float g_yn[(size_t)NB * CC * LL];           // 16 MB
__device__ float g_cos[(size_t)NB * LL * LL];          // 536 MB
__device__ float g_alpha[NL];
__device__ float g_off[NL];                            // -alpha - ln(Z_row)
__device__ float g_colpart[(size_t)LSPLIT * NB * LL];  // 1 MB partial col maxima
__device__ float g_loss_n[NB];

// ---------------- helpers ----------------------------------------------------
// exp(x) via FFMA-only exp2 (magic-number RNE round + degree-5 poly).
// Valid for x in roughly [-80, 80]; rel err <= ~3e-6. No MUFU.
__device__ __forceinline__ float fast_exp(float x) {
    float y = x * 1.4426950408889634f;            // x * log2(e)
    float t = y + 12582912.0f;                    // round-to-nearest-even
    int   n = __float_as_int(t) - 0x4B400000;     // integer part
    float f = y - (t - 12582912.0f);              // frac in [-0.5, 0.5]
    float p =            1.3333558146e-3f;
    p = fmaf(p, f, 9.6181291071e-3f);
    p = fmaf(p, f, 5.5504108664e-2f);
    p = fmaf(p, f, 2.4022650696e-1f);
    p = fmaf(p, f, 6.9314718056e-1f);
    p = fmaf(p, f, 1.0f);                         // ~2^f
    return __int_as_float(__float_as_int(p) + (n << 23));
}

__device__ __forceinline__ float block_reduce_sum_256(float v) {
    __shared__ float sh[8];
    int lane = threadIdx.x & 31, w = threadIdx.x >> 5;
    #pragma unroll
    for (int o = 16; o; o >>= 1) v += __shfl_xor_sync(0xffffffffu, v, o);
    if (lane == 0) sh[w] = v;
    __syncthreads();
    if (w == 0) {
        v = (lane < 8) ? sh[lane] : 0.f;
        #pragma unroll
        for (int o = 4; o; o >>= 1) v += __shfl_xor_sync(0xffffffffu, v, o);
    }
    return v;  // valid on warp 0
}

__device__ __forceinline__ float block_reduce_max_256(float v) {
    __shared__ float shm[8];
    int lane = threadIdx.x & 31, w = threadIdx.x >> 5;
    #pragma unroll
    for (int o = 16; o; o >>= 1) v = fmaxf(v, __shfl_xor_sync(0xffffffffu, v, o));
    if (lane == 0) shm[w] = v;
    __syncthreads();
    if (w == 0) {
        v = (lane < 8) ? shm[lane] : -INFINITY;
        #pragma unroll
        for (int o = 4; o; o >>= 1) v = fmaxf(v, __shfl_xor_sync(0xffffffffu, v, o));
    }
    return v;  // valid on warp 0
}

// ---------------- kernels ----------------------------------------------------

// y_mu[c] = mean over (n, l) of y
__global__ __launch_bounds__(256) void ymu_kernel(const float* __restrict__ y) {
    int c = blockIdx.x;
    float s = 0.f;
    for (int i = threadIdx.x; i < NB * LL; i += 256) {
        int n = i >> 12, l = i & (LL - 1);
        s += y[(size_t)n * CC * LL + (size_t)c * LL + l];
    }
    s = block_reduce_sum_256(s);
    if (threadIdx.x == 0) g_ymu[c] = s * (1.0f / (NB * LL));
}

// Center by y_mu, L2-normalize over channel dim.
// dst_sel resolves the destination INSIDE device code (device symbol address).
__global__ __launch_bounds__(256) void normalize_kernel(const float* __restrict__ src,
                                                        int dst_sel) {
    float* __restrict__ dst = dst_sel ? g_yn : g_xn;
    __shared__ float mu[CC];
    if (threadIdx.x < CC) mu[threadIdx.x] = g_ymu[threadIdx.x];
    __syncthreads();
    int idx = blockIdx.x * 256 + threadIdx.x;  // n*L + l
    int n = idx >> 12, l = idx & (LL - 1);
    size_t base = (size_t)n * CC * LL + l;
    float ss = 0.f;
    #pragma unroll 8
    for (int c = 0; c < CC; c++) {
        float v = src[base + (size_t)c * LL] - mu[c];
        ss += v * v;
    }
    float r = 1.0f / fmaxf(sqrtf(ss), 1e-12f);
    #pragma unroll 8
    for (int c = 0; c < CC; c++) {
        float v = src[base + (size_t)c * LL] - mu[c];
        dst[base + (size_t)c * LL] = v * r;
    }
}

// cos[n,l,m] = sum_c xn[n,c,l] * yn[n,c,m];   64x64 tile, K=128. Plain store.
__global__ __launch_bounds__(256) void gemm_cos_kernel() {
    __shared__ float As[16][64];
    __shared__ float Bs[16][64];
    int n  = blockIdx.z;
    int l0 = blockIdx.y * 64;
    int m0 = blockIdx.x * 64;
    int tid = threadIdx.x;
    int tx = tid & 15, ty = tid >> 4;

    const float* A = g_xn + (size_t)n * CC * LL;
    const float* B = g_yn + (size_t)n * CC * LL;

    float acc[4][4];
    #pragma unroll
    for (int i = 0; i < 4; i++)
        #pragma unroll
        for (int j = 0; j < 4; j++) acc[i][j] = 0.f;

    for (int k0 = 0; k0 < CC; k0 += 16) {
        #pragma unroll
        for (int i = 0; i < 4; i++) {
            int e = tid + i * 256;
            int r = e >> 6, cc = e & 63;
            As[r][cc] = A[(size_t)(k0 + r) * LL + l0 + cc];
            Bs[r][cc] = B[(size_t)(k0 + r) * LL + m0 + cc];
        }
        __syncthreads();
        #pragma unroll
        for (int kk = 0; kk < 16; kk++) {
            float a[4], b[4];
            #pragma unroll
            for (int i = 0; i < 4; i++) a[i] = As[kk][ty * 4 + i];
            #pragma unroll
            for (int j = 0; j < 4; j++) b[j] = Bs[kk][tx * 4 + j];
            #pragma unroll
            for (int i = 0; i < 4; i++)
                #pragma unroll
                for (int j = 0; j < 4; j++)
                    acc[i][j] = fmaf(a[i], b[j], acc[i][j]);
        }
        __syncthreads();
    }

    float* Cp = g_cos + (size_t)n * LL * LL;
    #pragma unroll
    for (int i = 0; i < 4; i++) {
        int l = l0 + ty * 4 + i;
        float4 v = make_float4(acc[i][0], acc[i][1], acc[i][2], acc[i][3]);
        *(float4*)(Cp + (size_t)l * LL + m0 + tx * 4) = v;
    }
}

// Per row l: rowmax -> dmin -> alpha; Z = sum_m exp(alpha*(cos-1)).
__global__ __launch_bounds__(256) void row_pass_kernel() {
    __shared__ float s_bcast;
    int row = blockIdx.x;                 // n*L + l
    int n = row >> 12, l = row & (LL - 1);
    const float* cr = g_cos + (size_t)n * LL * LL + (size_t)l * LL;
    int t = threadIdx.x;

    float4 v[4];
    #pragma unroll
    for (int i = 0; i < 4; i++)
        v[i] = *(const float4*)(cr + t * 4 + i * 1024);

    float mx = -INFINITY;
    #pragma unroll
    for (int i = 0; i < 4; i++) {
        mx = fmaxf(mx, fmaxf(fmaxf(v[i].x, v[i].y), fmaxf(v[i].z, v[i].w)));
    }
    mx = block_reduce_max_256(mx);
    if (threadIdx.x == 0) s_bcast = mx;
    __syncthreads();
    float rowmax = s_bcast;

    float dmin  = 1.0f - rowmax;
    float alpha = 2.0f / (dmin + EPS_BAND);

    float s = 0.f;
    #pragma unroll
    for (int i = 0; i < 4; i++) {
        s += fast_exp(alpha * (v[i].x - 1.0f));
        s += fast_exp(alpha * (v[i].y - 1.0f));
        s += fast_exp(alpha * (v[i].z - 1.0f));
        s += fast_exp(alpha * (v[i].w - 1.0f));
    }
    s = block_reduce_sum_256(s);
    if (threadIdx.x == 0) {
        g_alpha[row] = alpha;
        g_off[row]   = -alpha - logf(s);
    }
}

// Column pass: partial max over an l-chunk of (alpha_l*cos[l,m] + off_l).
__global__ __launch_bounds__(256) void col_pass_kernel() {
    int n = blockIdx.z;
    int m = blockIdx.x * 256 + threadIdx.x;
    int lbeg = blockIdx.y * (LL / LSPLIT);
    __shared__ float sA[128], sO[128];
    const float* Cp = g_cos + (size_t)n * LL * LL;
    float best = -INFINITY;
    for (int c = 0; c < (LL / LSPLIT) / 128; c++) {
        int lb = lbeg + c * 128;
        __syncthreads();
        if (threadIdx.x < 128) {
            sA[threadIdx.x] = g_alpha[n * LL + lb + threadIdx.x];
            sO[threadIdx.x] = g_off[n * LL + lb + threadIdx.x];
        }
        __syncthreads();
        #pragma unroll 8
        for (int li = 0; li < 128; li++) {
            float cv = Cp[(size_t)(lb + li) * LL + m];
            best = fmaxf(best, fmaf(sA[li], cv, sO[li]));
        }
    }
    g_colpart[((size_t)blockIdx.y * NB + n) * LL + m] = best;
}

// Per n: cx_n = mean_m exp(max over splits); loss_n = -log(cx_n + eps)
__global__ __launch_bounds__(256) void finalize_n_kernel() {
    int n = blockIdx.x;
    float s = 0.f;
    for (int m = threadIdx.x; m < LL; m += 256) {
        float best = -INFINITY;
        #pragma unroll
        for (int sp = 0; sp < LSPLIT; sp++)
            best = fmaxf(best, g_colpart[((size_t)sp * NB + n) * LL + m]);
        s += fast_exp(best);
    }
    s = block_reduce_sum_256(s);
    if (threadIdx.x == 0)
        g_loss_n[n] = -logf(s * (1.0f / LL) + EPS_BAND);
}

__global__ void final_kernel(float* __restrict__ out) {
    float s = 0.f;
    #pragma unroll
    for (int n = 0; n < NB; n++) s += g_loss_n[n];
    out[0] = s * (1.0f / NB);
}

// ---------------- launch ------------------------------------------------------
extern "C" void kernel_launch(void* const* d_in, const int* in_sizes, int n_in,
                              void* d_out, int out_size) {
    const float* x = (const float*)d_in[0];
    const float* y = (const float*)d_in[1];
    float* out = (float*)d_out;

    ymu_kernel<<<CC, 256>>>(y);
    normalize_kernel<<<NL / 256, 256>>>(x, 0);  // -> g_xn (resolved device-side)
    normalize_kernel<<<NL / 256, 256>>>(y, 1);  // -> g_yn (resolved device-side)
    gemm_cos_kernel<<<dim3(LL / 64, LL / 64, NB), 256>>>();
    row_pass_kernel<<<NL, 256>>>();
    col_pass_kernel<<<dim3(LL / 256, LSPLIT, NB), 256>>>();
    finalize_n_kernel<<<NB, 256>>>();
    final_kernel<<<1, 1>>>(out);
}

// round 8
// speedup vs baseline: 2.2870x; 2.2870x over previous
#include <cuda_runtime.h>
#include <cuda_fp16.h>
#include <math.h>
#include <stdint.h>

#define NB 8
#define CC 128
#define LL 4096
#define NL (NB * LL)          // 32768
#define LSPLIT 8
#define EPS_BAND 1e-5f

// GEMM tile
#define TM 128
#define TN 256
#define SSTRIDE 132                               // padded row stride in words
#define A_WORDS (TM * SSTRIDE)                    // 16896
#define B_WORDS (TN * SSTRIDE)                    // 33792
#define SMEM_BYTES ((A_WORDS + B_WORDS) * 4)      // 202752

// ---------------- scratch (device globals; device-code references only) ------
__device__ float  g_ymu[CC];
__device__ float  g_xn[(size_t)NB * LL * CC];          // K-major [n][l][c], tf32-rounded
__device__ float  g_yn[(size_t)NB * LL * CC];
__device__ __half g_cosh[(size_t)NB * LL * LL];        // 268 MB fp16 cos
__device__ float  g_alpha[NL];
__device__ float  g_off[NL];
__device__ float  g_colpart[(size_t)LSPLIT * NB * LL];
__device__ float  g_loss_n[NB];

// ---------------- helpers ------------------------------------------------------
__device__ __forceinline__ float to_tf32(float x) {
    uint32_t o;
    asm("cvt.rna.tf32.f32 %0, %1;" : "=r"(o) : "f"(x));
    return __uint_as_float(o);
}

__device__ __forceinline__ void mma_tf32(float* c, const uint32_t* a, const uint32_t* b) {
    asm volatile(
        "mma.sync.aligned.m16n8k8.row.col.f32.tf32.tf32.f32 "
        "{%0,%1,%2,%3}, {%4,%5,%6,%7}, {%8,%9}, {%0,%1,%2,%3};"
        : "+f"(c[0]), "+f"(c[1]), "+f"(c[2]), "+f"(c[3])
        : "r"(a[0]), "r"(a[1]), "r"(a[2]), "r"(a[3]), "r"(b[0]), "r"(b[1]));
}

__device__ __forceinline__ float fast_exp(float x) {
    float y = x * 1.4426950408889634f;
    float t = y + 12582912.0f;
    int   n = __float_as_int(t) - 0x4B400000;
    float f = y - (t - 12582912.0f);
    float p =            1.3333558146e-3f;
    p = fmaf(p, f, 9.6181291071e-3f);
    p = fmaf(p, f, 5.5504108664e-2f);
    p = fmaf(p, f, 2.4022650696e-1f);
    p = fmaf(p, f, 6.9314718056e-1f);
    p = fmaf(p, f, 1.0f);
    return __int_as_float(__float_as_int(p) + (n << 23));
}

__device__ __forceinline__ float block_reduce_sum_256(float v) {
    __shared__ float sh[8];
    int lane = threadIdx.x & 31, w = threadIdx.x >> 5;
    #pragma unroll
    for (int o = 16; o; o >>= 1) v += __shfl_xor_sync(0xffffffffu, v, o);
    if (lane == 0) sh[w] = v;
    __syncthreads();
    if (w == 0) {
        v = (lane < 8) ? sh[lane] : 0.f;
        #pragma unroll
        for (int o = 4; o; o >>= 1) v += __shfl_xor_sync(0xffffffffu, v, o);
    }
    return v;
}
__device__ __forceinline__ float block_reduce_max_256(float v) {
    __shared__ float shm[8];
    int lane = threadIdx.x & 31, w = threadIdx.x >> 5;
    #pragma unroll
    for (int o = 16; o; o >>= 1) v = fmaxf(v, __shfl_xor_sync(0xffffffffu, v, o));
    if (lane == 0) shm[w] = v;
    __syncthreads();
    if (w == 0) {
        v = (lane < 8) ? shm[lane] : -INFINITY;
        #pragma unroll
        for (int o = 4; o; o >>= 1) v = fmaxf(v, __shfl_xor_sync(0xffffffffu, v, o));
    }
    return v;
}

// ---------------- kernels ------------------------------------------------------

__global__ __launch_bounds__(256) void ymu_kernel(const float* __restrict__ y) {
    int c = blockIdx.x;
    float s = 0.f;
    for (int i = threadIdx.x; i < NB * LL; i += 256) {
        int n = i >> 12, l = i & (LL - 1);
        s += y[(size_t)n * CC * LL + (size_t)c * LL + l];
    }
    s = block_reduce_sum_256(s);
    if (threadIdx.x == 0) g_ymu[c] = s * (1.0f / (NB * LL));
}

// Center + L2-normalize; K-major [n][l][c] output, pre-rounded to tf32.
__global__ __launch_bounds__(256) void normalize_kernel(const float* __restrict__ src,
                                                        int dst_sel) {
    float* __restrict__ dst = dst_sel ? g_yn : g_xn;
    __shared__ float mu[CC];
    if (threadIdx.x < CC) mu[threadIdx.x] = g_ymu[threadIdx.x];
    __syncthreads();
    int idx = blockIdx.x * 256 + threadIdx.x;  // n*L + l
    int n = idx >> 12, l = idx & (LL - 1);
    size_t base = (size_t)n * CC * LL + l;
    float ss = 0.f;
    #pragma unroll 8
    for (int c = 0; c < CC; c++) {
        float v = src[base + (size_t)c * LL] - mu[c];
        ss += v * v;
    }
    float r = 1.0f / fmaxf(sqrtf(ss), 1e-12f);
    float4* drow = (float4*)(dst + ((size_t)n * LL + l) * CC);
    #pragma unroll 4
    for (int c0 = 0; c0 < CC; c0 += 4) {
        float4 o;
        o.x = to_tf32((src[base + (size_t)(c0 + 0) * LL] - mu[c0 + 0]) * r);
        o.y = to_tf32((src[base + (size_t)(c0 + 1) * LL] - mu[c0 + 1]) * r);
        o.z = to_tf32((src[base + (size_t)(c0 + 2) * LL] - mu[c0 + 2]) * r);
        o.w = to_tf32((src[base + (size_t)(c0 + 3) * LL] - mu[c0 + 3]) * r);
        drow[c0 >> 2] = o;
    }
}

// tf32 mma.sync GEMM: cos tile TM x TN, K=128; fp16 store via smem staging.
// Warp grid 4(m) x 4(n): each warp 32(m) x 64(n) using m16n8k8 fragments.
__global__ __launch_bounds__(512, 1) void gemm_cos_mma() {
    extern __shared__ float smf[];
    uint32_t* smu = (uint32_t*)smf;
    int tid = threadIdx.x;
    int w = tid >> 5, lane = tid & 31;
    int g = lane >> 2, t = lane & 3;
    int wm = w & 3, wn = w >> 2;
    int n = blockIdx.z, l0 = blockIdx.y * TM, m0 = blockIdx.x * TN;

    // Load A tile: TM rows x 128 floats (K-major), padded stride 132.
    const float4* Ag = (const float4*)(g_xn + ((size_t)n * LL + l0) * CC);
    #pragma unroll
    for (int it = 0; it < (TM * 32) / 512; it++) {
        int id = tid + it * 512; int r = id >> 5, q = id & 31;
        *(float4*)(smf + r * SSTRIDE + q * 4) = Ag[r * 32 + q];
    }
    // Load B tile: TN rows x 128 floats.
    const float4* Bg = (const float4*)(g_yn + ((size_t)n * LL + m0) * CC);
    #pragma unroll
    for (int it = 0; it < (TN * 32) / 512; it++) {
        int id = tid + it * 512; int r = id >> 5, q = id & 31;
        *(float4*)(smf + A_WORDS + r * SSTRIDE + q * 4) = Bg[r * 32 + q];
    }
    __syncthreads();

    float acc[2][8][4];
    #pragma unroll
    for (int mt = 0; mt < 2; mt++)
        #pragma unroll
        for (int nt = 0; nt < 8; nt++)
            #pragma unroll
            for (int j = 0; j < 4; j++) acc[mt][nt][j] = 0.f;

    const uint32_t* Au = smu;
    const uint32_t* Bu = smu + A_WORDS;

    #pragma unroll
    for (int ks = 0; ks < 16; ks++) {
        int k0 = ks * 8;
        uint32_t a[2][4], b[8][2];
        #pragma unroll
        for (int mt = 0; mt < 2; mt++) {
            int rb = (wm * 32 + mt * 16 + g) * SSTRIDE + k0 + t;
            a[mt][0] = Au[rb];
            a[mt][1] = Au[rb + 8 * SSTRIDE];
            a[mt][2] = Au[rb + 4];
            a[mt][3] = Au[rb + 8 * SSTRIDE + 4];
        }
        #pragma unroll
        for (int nt = 0; nt < 8; nt++) {
            int rb = (wn * 64 + nt * 8 + g) * SSTRIDE + k0 + t;
            b[nt][0] = Bu[rb];
            b[nt][1] = Bu[rb + 4];
        }
        #pragma unroll
        for (int mt = 0; mt < 2; mt++)
            #pragma unroll
            for (int nt = 0; nt < 8; nt++)
                mma_tf32(acc[mt][nt], a[mt], b[nt]);
    }

    // Epilogue: stage fp16 through smem (reuse A region), then coalesced STG.
    __syncthreads();
    #pragma unroll
    for (int mt = 0; mt < 2; mt++) {
        #pragma unroll
        for (int nt = 0; nt < 8; nt++) {
            int off = wn * 32 + nt * 4 + t;
            int r0  = wm * 32 + mt * 16 + g;
            __half2 h01 = __floats2half2_rn(acc[mt][nt][0], acc[mt][nt][1]);
            __half2 h23 = __floats2half2_rn(acc[mt][nt][2], acc[mt][nt][3]);
            smu[r0 * SSTRIDE + off]       = *(uint32_t*)&h01;
            smu[(r0 + 8) * SSTRIDE + off] = *(uint32_t*)&h23;
        }
    }
    __syncthreads();
    __half* dstbase = g_cosh + ((size_t)n * LL + l0) * LL + m0;
    #pragma unroll
    for (int it = 0; it < (TM * 32) / 512; it++) {
        int id = tid + it * 512; int r = id >> 5, q = id & 31;
        uint4 v = *(uint4*)(smu + r * SSTRIDE + q * 4);
        *(uint4*)(dstbase + (size_t)r * LL + q * 8) = v;
    }
}

// Per row: rowmax -> alpha; Z = sum exp(alpha*(cos-1)); fp16 row read.
__global__ __launch_bounds__(256) void row_pass_kernel() {
    __shared__ float s_bcast;
    int row = blockIdx.x;  // n*L + l
    const uint4* cr = (const uint4*)(g_cosh + (size_t)row * LL);
    int t = threadIdx.x;

    uint4 u[2];
    u[0] = cr[t * 2];
    u[1] = cr[t * 2 + 1];

    float2 f[8];
    #pragma unroll
    for (int i = 0; i < 2; i++) {
        f[i * 4 + 0] = __half22float2(*(__half2*)&u[i].x);
        f[i * 4 + 1] = __half22float2(*(__half2*)&u[i].y);
        f[i * 4 + 2] = __half22float2(*(__half2*)&u[i].z);
        f[i * 4 + 3] = __half22float2(*(__half2*)&u[i].w);
    }
    float mx = -INFINITY;
    #pragma unroll
    for (int i = 0; i < 8; i++) mx = fmaxf(mx, fmaxf(f[i].x, f[i].y));
    mx = block_reduce_max_256(mx);
    if (threadIdx.x == 0) s_bcast = mx;
    __syncthreads();
    float rowmax = s_bcast;

    float dmin  = 1.0f - rowmax;
    float alpha = 2.0f / (dmin + EPS_BAND);

    float s = 0.f;
    #pragma unroll
    for (int i = 0; i < 8; i++) {
        s += fast_exp(alpha * (f[i].x - 1.0f));
        s += fast_exp(alpha * (f[i].y - 1.0f));
    }
    s = block_reduce_sum_256(s);
    if (threadIdx.x == 0) {
        g_alpha[row] = alpha;
        g_off[row]   = -alpha - logf(s);
    }
}

// Column pass over fp16 cos: partial max of (alpha_l*cos + off_l), half2/thread.
__global__ __launch_bounds__(256) void col_pass_kernel() {
    int n = blockIdx.z;
    int m2 = blockIdx.x * 256 + threadIdx.x;       // half2 index (grid.x = LL/512)
    int lbeg = blockIdx.y * (LL / LSPLIT);
    __shared__ float sA[128], sO[128];
    const __half* Cp = g_cosh + (size_t)n * LL * LL;
    float bx = -INFINITY, by = -INFINITY;
    for (int c = 0; c < (LL / LSPLIT) / 128; c++) {
        int lb = lbeg + c * 128;
        __syncthreads();
        if (threadIdx.x < 128) {
            sA[threadIdx.x] = g_alpha[n * LL + lb + threadIdx.x];
            sO[threadIdx.x] = g_off[n * LL + lb + threadIdx.x];
        }
        __syncthreads();
        #pragma unroll 8
        for (int li = 0; li < 128; li++) {
            __half2 hp = ((const __half2*)(Cp + (size_t)(lb + li) * LL))[m2];
            float2 fv = __half22float2(hp);
            bx = fmaxf(bx, fmaf(sA[li], fv.x, sO[li]));
            by = fmaxf(by, fmaf(sA[li], fv.y, sO[li]));
        }
    }
    float* out = g_colpart + ((size_t)blockIdx.y * NB + n) * LL;
    out[2 * m2]     = bx;
    out[2 * m2 + 1] = by;
}

__global__ __launch_bounds__(256) void finalize_n_kernel() {
    int n = blockIdx.x;
    float s = 0.f;
    for (int m = threadIdx.x; m < LL; m += 256) {
        float best = -INFINITY;
        #pragma unroll
        for (int sp = 0; sp < LSPLIT; sp++)
            best = fmaxf(best, g_colpart[((size_t)sp * NB + n) * LL + m]);
        s += fast_exp(best);
    }
    s = block_reduce_sum_256(s);
    if (threadIdx.x == 0)
        g_loss_n[n] = -logf(s * (1.0f / LL) + EPS_BAND);
}

__global__ void final_kernel(float* __restrict__ out) {
    float s = 0.f;
    #pragma unroll
    for (int n = 0; n < NB; n++) s += g_loss_n[n];
    out[0] = s * (1.0f / NB);
}

// ---------------- launch ------------------------------------------------------
extern "C" void kernel_launch(void* const* d_in, const int* in_sizes, int n_in,
                              void* d_out, int out_size) {
    const float* x = (const float*)d_in[0];
    const float* y = (const float*)d_in[1];
    float* out = (float*)d_out;

    cudaFuncSetAttribute(gemm_cos_mma, cudaFuncAttributeMaxDynamicSharedMemorySize,
                         SMEM_BYTES);

    ymu_kernel<<<CC, 256>>>(y);
    normalize_kernel<<<NL / 256, 256>>>(x, 0);
    normalize_kernel<<<NL / 256, 256>>>(y, 1);
    gemm_cos_mma<<<dim3(LL / TN, LL / TM, NB), 512, SMEM_BYTES>>>();
    row_pass_kernel<<<NL, 256>>>();
    col_pass_kernel<<<dim3(LL / 512, LSPLIT, NB), 256>>>();
    finalize_n_kernel<<<NB, 256>>>();
    final_kernel<<<1, 1>>>(out);
}

// round 11
// speedup vs baseline: 2.9063x; 1.2708x over previous
#include <cuda_runtime.h>
#include <cuda_fp16.h>
#include <math.h>
#include <stdint.h>

#define NB 8
#define CC 128
#define LL 4096
#define NL (NB * LL)          // 32768
#define LSPLIT 8
#define EPS_BAND 1e-5f

// GEMM tile
#define TM 128
#define TN 256
#define SSH 136                                   // padded row stride in halves
#define A_HALFS (TM * SSH)                        // 17408
#define B_HALFS (TN * SSH)                        // 34816
#define SMEM_BYTES ((A_HALFS + B_HALFS) * 2)      // 104448
#define STG_STRIDE 132                            // staging stride in words

// ---------------- scratch (device globals; device-code references only) ------
__device__ float  g_ymu[CC];
__device__ __half g_xh[(size_t)NB * LL * CC];          // K-major [n][l][c] fp16, 8 MB
__device__ __half g_yh[(size_t)NB * LL * CC];          // 8 MB
__device__ __half g_cosh[(size_t)NB * LL * LL];        // 268 MB fp16 cos
__device__ float  g_alpha[NL];
__device__ float  g_off[NL];
__device__ float  g_colpart[(size_t)LSPLIT * NB * LL];
__device__ float  g_loss_n[NB];

// ---------------- helpers ------------------------------------------------------
__device__ __forceinline__ void mma_f16(float* c, const uint32_t* a, const uint32_t* b) {
    asm volatile(
        "mma.sync.aligned.m16n8k16.row.col.f32.f16.f16.f32 "
        "{%0,%1,%2,%3}, {%4,%5,%6,%7}, {%8,%9}, {%0,%1,%2,%3};"
        : "+f"(c[0]), "+f"(c[1]), "+f"(c[2]), "+f"(c[3])
        : "r"(a[0]), "r"(a[1]), "r"(a[2]), "r"(a[3]), "r"(b[0]), "r"(b[1]));
}

__device__ __forceinline__ float fast_exp(float x) {
    float y = x * 1.4426950408889634f;
    float t = y + 12582912.0f;
    int   n = __float_as_int(t) - 0x4B400000;
    float f = y - (t - 12582912.0f);
    float p =            1.3333558146e-3f;
    p = fmaf(p, f, 9.6181291071e-3f);
    p = fmaf(p, f, 5.5504108664e-2f);
    p = fmaf(p, f, 2.4022650696e-1f);
    p = fmaf(p, f, 6.9314718056e-1f);
    p = fmaf(p, f, 1.0f);
    return __int_as_float(__float_as_int(p) + (n << 23));
}

__device__ __forceinline__ float block_reduce_sum_256(float v) {
    __shared__ float sh[8];
    int lane = threadIdx.x & 31, w = threadIdx.x >> 5;
    #pragma unroll
    for (int o = 16; o; o >>= 1) v += __shfl_xor_sync(0xffffffffu, v, o);
    if (lane == 0) sh[w] = v;
    __syncthreads();
    if (w == 0) {
        v = (lane < 8) ? sh[lane] : 0.f;
        #pragma unroll
        for (int o = 4; o; o >>= 1) v += __shfl_xor_sync(0xffffffffu, v, o);
    }
    return v;
}
__device__ __forceinline__ float block_reduce_max_256(float v) {
    __shared__ float shm[8];
    int lane = threadIdx.x & 31, w = threadIdx.x >> 5;
    #pragma unroll
    for (int o = 16; o; o >>= 1) v = fmaxf(v, __shfl_xor_sync(0xffffffffu, v, o));
    if (lane == 0) shm[w] = v;
    __syncthreads();
    if (w == 0) {
        v = (lane < 8) ? shm[lane] : -INFINITY;
        #pragma unroll
        for (int o = 4; o; o >>= 1) v = fmaxf(v, __shfl_xor_sync(0xffffffffu, v, o));
    }
    return v;
}

// ---------------- kernels ------------------------------------------------------

__global__ __launch_bounds__(256) void ymu_kernel(const float* __restrict__ y) {
    int c = blockIdx.x;
    float s = 0.f;
    for (int i = threadIdx.x; i < NB * LL; i += 256) {
        int n = i >> 12, l = i & (LL - 1);
        s += y[(size_t)n * CC * LL + (size_t)c * LL + l];
    }
    s = block_reduce_sum_256(s);
    if (threadIdx.x == 0) g_ymu[c] = s * (1.0f / (NB * LL));
}

// Center + L2-normalize; K-major [n][l][c] fp16 output.
__global__ __launch_bounds__(256) void normalize_kernel(const float* __restrict__ src,
                                                        int dst_sel) {
    __half* __restrict__ dst = dst_sel ? g_yh : g_xh;
    __shared__ float mu[CC];
    if (threadIdx.x < CC) mu[threadIdx.x] = g_ymu[threadIdx.x];
    __syncthreads();
    int idx = blockIdx.x * 256 + threadIdx.x;  // n*L + l
    int n = idx >> 12, l = idx & (LL - 1);
    size_t base = (size_t)n * CC * LL + l;
    float ss = 0.f;
    #pragma unroll 8
    for (int c = 0; c < CC; c++) {
        float v = src[base + (size_t)c * LL] - mu[c];
        ss += v * v;
    }
    float r = 1.0f / fmaxf(sqrtf(ss), 1e-12f);
    uint4* drow = (uint4*)(dst + ((size_t)n * LL + l) * CC);
    #pragma unroll 2
    for (int c0 = 0; c0 < CC; c0 += 8) {
        __half2 p0 = __floats2half2_rn((src[base + (size_t)(c0 + 0) * LL] - mu[c0 + 0]) * r,
                                       (src[base + (size_t)(c0 + 1) * LL] - mu[c0 + 1]) * r);
        __half2 p1 = __floats2half2_rn((src[base + (size_t)(c0 + 2) * LL] - mu[c0 + 2]) * r,
                                       (src[base + (size_t)(c0 + 3) * LL] - mu[c0 + 3]) * r);
        __half2 p2 = __floats2half2_rn((src[base + (size_t)(c0 + 4) * LL] - mu[c0 + 4]) * r,
                                       (src[base + (size_t)(c0 + 5) * LL] - mu[c0 + 5]) * r);
        __half2 p3 = __floats2half2_rn((src[base + (size_t)(c0 + 6) * LL] - mu[c0 + 6]) * r,
                                       (src[base + (size_t)(c0 + 7) * LL] - mu[c0 + 7]) * r);
        uint4 o;
        o.x = *(uint32_t*)&p0; o.y = *(uint32_t*)&p1;
        o.z = *(uint32_t*)&p2; o.w = *(uint32_t*)&p3;
        drow[c0 >> 3] = o;
    }
}

// fp16 mma.sync GEMM: cos tile TM x TN, K=128, fp32 accum; fp16 store via smem stage.
// Warp grid 4(m) x 4(n): each warp 32(m) x 64(n) via m16n8k16 fragments.
__global__ __launch_bounds__(512, 1) void gemm_cos_mma() {
    extern __shared__ __half smh[];
    uint32_t* smu = (uint32_t*)smh;
    int tid = threadIdx.x;
    int w = tid >> 5, lane = tid & 31;
    int g = lane >> 2, t = lane & 3;
    int wm = w & 3, wn = w >> 2;
    int n = blockIdx.z, l0 = blockIdx.y * TM, m0 = blockIdx.x * TN;

    // Load A tile: TM rows x 128 halves (K-major), padded stride SSH.
    const uint4* Ag = (const uint4*)(g_xh + ((size_t)n * LL + l0) * CC);
    #pragma unroll
    for (int it = 0; it < (TM * 16) / 512; it++) {
        int id = tid + it * 512; int r = id >> 4, q = id & 15;
        *(uint4*)(smh + r * SSH + q * 8) = Ag[r * 16 + q];
    }
    // Load B tile: TN rows x 128 halves.
    const uint4* Bg = (const uint4*)(g_yh + ((size_t)n * LL + m0) * CC);
    #pragma unroll
    for (int it = 0; it < (TN * 16) / 512; it++) {
        int id = tid + it * 512; int r = id >> 4, q = id & 15;
        *(uint4*)(smh + A_HALFS + r * SSH + q * 8) = Bg[r * 16 + q];
    }
    __syncthreads();

    float acc[2][8][4];
    #pragma unroll
    for (int mt = 0; mt < 2; mt++)
        #pragma unroll
        for (int nt = 0; nt < 8; nt++)
            #pragma unroll
            for (int j = 0; j < 4; j++) acc[mt][nt][j] = 0.f;

    const __half* Ah = smh;
    const __half* Bh = smh + A_HALFS;

    #pragma unroll
    for (int ks = 0; ks < 8; ks++) {           // 8 chunks of k16
        int kh = ks * 16;
        uint32_t a[2][4], b[8][2];
        #pragma unroll
        for (int mt = 0; mt < 2; mt++) {
            const __half* rp = Ah + (wm * 32 + mt * 16 + g) * SSH + kh + 2 * t;
            a[mt][0] = *(const uint32_t*)rp;
            a[mt][1] = *(const uint32_t*)(rp + 8 * SSH);
            a[mt][2] = *(const uint32_t*)(rp + 8);
            a[mt][3] = *(const uint32_t*)(rp + 8 * SSH + 8);
        }
        #pragma unroll
        for (int nt = 0; nt < 8; nt++) {
            const __half* rp = Bh + (wn * 64 + nt * 8 + g) * SSH + kh + 2 * t;
            b[nt][0] = *(const uint32_t*)rp;
            b[nt][1] = *(const uint32_t*)(rp + 8);
        }
        #pragma unroll
        for (int mt = 0; mt < 2; mt++)
            #pragma unroll
            for (int nt = 0; nt < 8; nt++)
                mma_f16(acc[mt][nt], a[mt], b[nt]);
    }

    // Epilogue: stage fp16 tile in smem (reuse operand region), coalesced STG.
    __syncthreads();
    #pragma unroll
    for (int mt = 0; mt < 2; mt++) {
        #pragma unroll
        for (int nt = 0; nt < 8; nt++) {
            int off = wn * 32 + nt * 4 + t;
            int r0  = wm * 32 + mt * 16 + g;
            __half2 h01 = __floats2half2_rn(acc[mt][nt][0], acc[mt][nt][1]);
            __half2 h23 = __floats2half2_rn(acc[mt][nt][2], acc[mt][nt][3]);
            smu[r0 * STG_STRIDE + off]       = *(uint32_t*)&h01;
            smu[(r0 + 8) * STG_STRIDE + off] = *(uint32_t*)&h23;
        }
    }
    __syncthreads();
    __half* dstbase = g_cosh + ((size_t)n * LL + l0) * LL + m0;
    #pragma unroll
    for (int it = 0; it < (TM * 32) / 512; it++) {
        int id = tid + it * 512; int r = id >> 5, q = id & 31;
        uint4 v = *(uint4*)(smu + r * STG_STRIDE + q * 4);
        *(uint4*)(dstbase + (size_t)r * LL + q * 8) = v;
    }
}

// Per row: rowmax -> alpha; Z = sum exp(alpha*(cos-1)); fp16 row read.
__global__ __launch_bounds__(256) void row_pass_kernel() {
    __shared__ float s_bcast;
    int row = blockIdx.x;  // n*L + l
    const uint4* cr = (const uint4*)(g_cosh + (size_t)row * LL);
    int t = threadIdx.x;

    uint4 u[2];
    u[0] = cr[t * 2];
    u[1] = cr[t * 2 + 1];

    float2 f[8];
    #pragma unroll
    for (int i = 0; i < 2; i++) {
        f[i * 4 + 0] = __half22float2(*(__half2*)&u[i].x);
        f[i * 4 + 1] = __half22float2(*(__half2*)&u[i].y);
        f[i * 4 + 2] = __half22float2(*(__half2*)&u[i].z);
        f[i * 4 + 3] = __half22float2(*(__half2*)&u[i].w);
    }
    float mx = -INFINITY;
    #pragma unroll
    for (int i = 0; i < 8; i++) mx = fmaxf(mx, fmaxf(f[i].x, f[i].y));
    mx = block_reduce_max_256(mx);
    if (threadIdx.x == 0) s_bcast = mx;
    __syncthreads();
    float rowmax = s_bcast;

    float dmin  = 1.0f - rowmax;
    float alpha = 2.0f / (dmin + EPS_BAND);

    float s = 0.f;
    #pragma unroll
    for (int i = 0; i < 8; i++) {
        s += fast_exp(alpha * (f[i].x - 1.0f));
        s += fast_exp(alpha * (f[i].y - 1.0f));
    }
    s = block_reduce_sum_256(s);
    if (threadIdx.x == 0) {
        g_alpha[row] = alpha;
        g_off[row]   = -alpha - logf(s);
    }
}

// Column pass over fp16 cos: partial max of (alpha_l*cos + off_l), half2/thread.
__global__ __launch_bounds__(256) void col_pass_kernel() {
    int n = blockIdx.z;
    int m2 = blockIdx.x * 256 + threadIdx.x;       // half2 index (grid.x = LL/512)
    int lbeg = blockIdx.y * (LL / LSPLIT);
    __shared__ float sA[128], sO[128];
    const __half* Cp = g_cosh + (size_t)n * LL * LL;
    float bx = -INFINITY, by = -INFINITY;
    for (int c = 0; c < (LL / LSPLIT) / 128; c++) {
        int lb = lbeg + c * 128;
        __syncthreads();
        if (threadIdx.x < 128) {
            sA[threadIdx.x] = g_alpha[n * LL + lb + threadIdx.x];
            sO[threadIdx.x] = g_off[n * LL + lb + threadIdx.x];
        }
        __syncthreads();
        #pragma unroll 8
        for (int li = 0; li < 128; li++) {
            __half2 hp = ((const __half2*)(Cp + (size_t)(lb + li) * LL))[m2];
            float2 fv = __half22float2(hp);
            bx = fmaxf(bx, fmaf(sA[li], fv.x, sO[li]));
            by = fmaxf(by, fmaf(sA[li], fv.y, sO[li]));
        }
    }
    float* out = g_colpart + ((size_t)blockIdx.y * NB + n) * LL;
    out[2 * m2]     = bx;
    out[2 * m2 + 1] = by;
}

__global__ __launch_bounds__(256) void finalize_n_kernel() {
    int n = blockIdx.x;
    float s = 0.f;
    for (int m = threadIdx.x; m < LL; m += 256) {
        float best = -INFINITY;
        #pragma unroll
        for (int sp = 0; sp < LSPLIT; sp++)
            best = fmaxf(best, g_colpart[((size_t)sp * NB + n) * LL + m]);
        s += fast_exp(best);
    }
    s = block_reduce_sum_256(s);
    if (threadIdx.x == 0)
        g_loss_n[n] = -logf(s * (1.0f / LL) + EPS_BAND);
}

__global__ void final_kernel(float* __restrict__ out) {
    float s = 0.f;
    #pragma unroll
    for (int n = 0; n < NB; n++) s += g_loss_n[n];
    out[0] = s * (1.0f / NB);
}

// ---------------- launch ------------------------------------------------------
extern "C" void kernel_launch(void* const* d_in, const int* in_sizes, int n_in,
                              void* d_out, int out_size) {
    const float* x = (const float*)d_in[0];
    const float* y = (const float*)d_in[1];
    float* out = (float*)d_out;

    cudaFuncSetAttribute(gemm_cos_mma, cudaFuncAttributeMaxDynamicSharedMemorySize,
                         SMEM_BYTES);

    ymu_kernel<<<CC, 256>>>(y);
    normalize_kernel<<<NL / 256, 256>>>(x, 0);
    normalize_kernel<<<NL / 256, 256>>>(y, 1);
    gemm_cos_mma<<<dim3(LL / TN, LL / TM, NB), 512, SMEM_BYTES>>>();
    row_pass_kernel<<<NL, 256>>>();
    col_pass_kernel<<<dim3(LL / 512, LSPLIT, NB), 256>>>();
    finalize_n_kernel<<<NB, 256>>>();
    final_kernel<<<1, 1>>>(out);
}